// round 2
// baseline (speedup 1.0000x reference)
#include <cuda_runtime.h>
#include <math.h>

#define L_LAYERS 2
#define NNEI 120
#define ED 64
#define HD 128
#define FDIM 384          // 3*HD
#define NW 16
#define NTHREADS (NW * 32)
#define SCALING 0.08838834764831845f   // HD^-0.5
#define LN_EPS 1e-5f

// shared memory layout (in floats)
#define OFF_SX   0                         // 120*64   = 7680
#define OFF_SQ   7680                      // 120*128  = 15360 (q, later o)
#define OFF_SKT  23040                     // 128*120  = 15360 (k transposed)
#define OFF_SV   38400                     // 120*128  = 15360
#define OFF_BUF  53760                     // max(2048 weight chunk, 16*2*120 aw) = 3840
#define OFF_R    57600                     // 120*3 = 360
#define OFF_MASK 57960                     // 120
#define SMEM_FLOATS 58080                  // 232320 bytes <= 232448 limit

__device__ __forceinline__ float warp_sum(float v) {
    #pragma unroll
    for (int o = 16; o; o >>= 1) v += __shfl_xor_sync(0xffffffffu, v, o);
    return v;
}
__device__ __forceinline__ float warp_max(float v) {
    #pragma unroll
    for (int o = 16; o; o >>= 1) v = fmaxf(v, __shfl_xor_sync(0xffffffffu, v, o));
    return v;
}

// softmax + mask + angle weighting for one attention row; lane owns m=4*lane..+3
__device__ __forceinline__ void softmax_row(float4 a, int n, int lane, bool kvalid,
                                            const float* smask, const float* sr,
                                            float* awrow) {
    const float NEG = -1e30f;
    float lg[4] = {a.x, a.y, a.z, a.w};
    float mx = NEG;
    #pragma unroll
    for (int c = 0; c < 4; c++) {
        int m = 4 * lane + c;
        bool ok = kvalid && (smask[m & 127] > 0.5f);
        lg[c] = ok ? lg[c] : NEG;
        mx = fmaxf(mx, lg[c]);
    }
    mx = warp_max(mx);
    float ex[4]; float s = 0.f;
    #pragma unroll
    for (int c = 0; c < 4; c++) { ex[c] = __expf(lg[c] - mx); s += ex[c]; }
    s = warp_sum(s);
    float inv = 1.0f / s;
    float qm = smask[n];
    float rn0 = sr[n * 3 + 0], rn1 = sr[n * 3 + 1], rn2 = sr[n * 3 + 2];
    if (kvalid) {
        float pv[4];
        #pragma unroll
        for (int c = 0; c < 4; c++) {
            int m = 4 * lane + c;
            float ang = rn0 * sr[m * 3 + 0] + rn1 * sr[m * 3 + 1] + rn2 * sr[m * 3 + 2];
            pv[c] = ex[c] * inv * qm * ang;
        }
        ((float4*)awrow)[lane] = make_float4(pv[0], pv[1], pv[2], pv[3]);
    }
}

__global__ __launch_bounds__(NTHREADS, 1)
void nwa_kernel(const float* __restrict__ G,
                const int* __restrict__ maskp,          // bool arrives as int32
                const float* __restrict__ rp,
                const float* __restrict__ in_w, const float* __restrict__ in_b,
                const float* __restrict__ out_w, const float* __restrict__ out_b,
                const float* __restrict__ ln_g, const float* __restrict__ ln_b,
                float* __restrict__ out)
{
    extern __shared__ float sm[];
    float* sx   = sm + OFF_SX;
    float* sq   = sm + OFF_SQ;
    float* skT  = sm + OFF_SKT;
    float* sv   = sm + OFF_SV;
    float* sbuf = sm + OFF_BUF;
    float* sr   = sm + OFF_R;
    float* smask = sm + OFF_MASK;
    float4* sx4 = (float4*)sx;

    const int b = blockIdx.x;
    const int tid = threadIdx.x;
    const int w = tid >> 5;
    const int lane = tid & 31;

    // ---- load per-batch inputs ----
    {
        const float4* Gx = (const float4*)(G + (size_t)b * NNEI * ED);
        for (int i = tid; i < NNEI * ED / 4; i += NTHREADS) sx4[i] = Gx[i];
        const float* rb = rp + (size_t)b * NNEI * 3;
        for (int i = tid; i < NNEI * 3; i += NTHREADS) sr[i] = rb[i];
        if (tid < NNEI) smask[tid] = maskp[(size_t)b * NNEI + tid] ? 1.0f : 0.0f;
    }
    __syncthreads();

    for (int l = 0; l < L_LAYERS; l++) {
        // ================= Phase A: qkv = x @ in_w + in_b =================
        const float* Wl = in_w + (size_t)l * ED * FDIM;
        for (int fc = 0; fc < FDIM / 32; fc++) {
            for (int idx = tid; idx < ED * 32; idx += NTHREADS) {
                int e = idx >> 5, j = idx & 31;
                sbuf[idx] = Wl[e * FDIM + fc * 32 + j];
            }
            __syncthreads();
            float acc[8];
            #pragma unroll
            for (int i = 0; i < 8; i++) acc[i] = 0.f;
            #pragma unroll
            for (int et = 0; et < 8; et++) {
                float wr[8];
                #pragma unroll
                for (int k2 = 0; k2 < 8; k2++) wr[k2] = sbuf[(et * 8 + k2) * 32 + lane];
                #pragma unroll
                for (int i = 0; i < 8; i++) {
                    int n = w + 16 * i;
                    if (n < NNEI) {
                        float4 x0 = sx4[n * 16 + et * 2];
                        float4 x1 = sx4[n * 16 + et * 2 + 1];
                        acc[i] = fmaf(wr[0], x0.x, acc[i]);
                        acc[i] = fmaf(wr[1], x0.y, acc[i]);
                        acc[i] = fmaf(wr[2], x0.z, acc[i]);
                        acc[i] = fmaf(wr[3], x0.w, acc[i]);
                        acc[i] = fmaf(wr[4], x1.x, acc[i]);
                        acc[i] = fmaf(wr[5], x1.y, acc[i]);
                        acc[i] = fmaf(wr[6], x1.z, acc[i]);
                        acc[i] = fmaf(wr[7], x1.w, acc[i]);
                    }
                }
            }
            int f = fc * 32 + lane;
            float bv = in_b[l * FDIM + f];
            #pragma unroll
            for (int i = 0; i < 8; i++) {
                int n = w + 16 * i;
                if (n < NNEI) {
                    float v = acc[i] + bv;
                    if (f < HD)            sq[n * HD + f] = v;
                    else if (f < 2 * HD)   skT[(f - HD) * NNEI + n] = v;
                    else                   sv[n * HD + (f - 2 * HD)] = v;
                }
            }
            __syncthreads();
        }

        // ================= Phase B: l2norm rows of q, k, v =================
        for (int task = w; task < 3 * NNEI; task += NW) {
            int type = task / NNEI;   // 0=q, 1=k, 2=v
            int n = task % NNEI;
            if (type != 1) {
                float* base = (type == 0 ? sq : sv) + n * HD;
                float4 vv = ((float4*)base)[lane];
                float s = vv.x * vv.x + vv.y * vv.y + vv.z * vv.z + vv.w * vv.w;
                s = warp_sum(s);
                float sc = 1.0f / fmaxf(sqrtf(s), 1e-12f);
                if (type == 0) sc *= SCALING;
                vv.x *= sc; vv.y *= sc; vv.z *= sc; vv.w *= sc;
                ((float4*)base)[lane] = vv;
            } else {
                float v0 = skT[(lane +  0) * NNEI + n];
                float v1 = skT[(lane + 32) * NNEI + n];
                float v2 = skT[(lane + 64) * NNEI + n];
                float v3 = skT[(lane + 96) * NNEI + n];
                float s = v0 * v0 + v1 * v1 + v2 * v2 + v3 * v3;
                s = warp_sum(s);
                float sc = 1.0f / fmaxf(sqrtf(s), 1e-12f);
                skT[(lane +  0) * NNEI + n] = v0 * sc;
                skT[(lane + 32) * NNEI + n] = v1 * sc;
                skT[(lane + 64) * NNEI + n] = v2 * sc;
                skT[(lane + 96) * NNEI + n] = v3 * sc;
            }
        }
        __syncthreads();

        // ========= Phase C+E: attention (2 query rows per warp per group) =========
        const bool kvalid = (lane < 30);   // lane owns m = 4*lane..4*lane+3 (<120)
        for (int g = 0; g < 4; g++) {
            int base = g * 32 + w * 2;
            if (base < NNEI) {
                float4 a0 = make_float4(0, 0, 0, 0), a1 = make_float4(0, 0, 0, 0);
                for (int h = 0; h < HD; h++) {
                    float4 k4 = kvalid ? ((const float4*)(skT + h * NNEI))[lane]
                                       : make_float4(0, 0, 0, 0);
                    float q0 = sq[base * HD + h];
                    float q1 = sq[(base + 1) * HD + h];
                    a0.x = fmaf(q0, k4.x, a0.x); a0.y = fmaf(q0, k4.y, a0.y);
                    a0.z = fmaf(q0, k4.z, a0.z); a0.w = fmaf(q0, k4.w, a0.w);
                    a1.x = fmaf(q1, k4.x, a1.x); a1.y = fmaf(q1, k4.y, a1.y);
                    a1.z = fmaf(q1, k4.z, a1.z); a1.w = fmaf(q1, k4.w, a1.w);
                }
                float* aw0 = sbuf + w * 240;
                float* aw1 = aw0 + NNEI;
                softmax_row(a0, base,     lane, kvalid, smask, sr, aw0);
                softmax_row(a1, base + 1, lane, kvalid, smask, sr, aw1);
                __syncwarp();
                // o = aw @ v ; lane owns h = 4*lane..+3
                float4 o0 = make_float4(0, 0, 0, 0), o1 = make_float4(0, 0, 0, 0);
                for (int m = 0; m < NNEI; m++) {
                    float4 v4 = ((const float4*)(sv + m * HD))[lane];
                    float p0 = aw0[m], p1 = aw1[m];
                    o0.x = fmaf(p0, v4.x, o0.x); o0.y = fmaf(p0, v4.y, o0.y);
                    o0.z = fmaf(p0, v4.z, o0.z); o0.w = fmaf(p0, v4.w, o0.w);
                    o1.x = fmaf(p1, v4.x, o1.x); o1.y = fmaf(p1, v4.y, o1.y);
                    o1.z = fmaf(p1, v4.z, o1.z); o1.w = fmaf(p1, v4.w, o1.w);
                }
                ((float4*)(sq + base * HD))[lane] = o0;          // overwrite q with o
                ((float4*)(sq + (base + 1) * HD))[lane] = o1;
            }
            __syncwarp();
        }
        __syncthreads();

        // ====== Phase F: x = LN(residual + o @ out_w + out_b) ======
        float accA[8], accB[8];
        #pragma unroll
        for (int i = 0; i < 8; i++) { accA[i] = 0.f; accB[i] = 0.f; }
        const float* Ow = out_w + (size_t)l * HD * ED;
        for (int hc = 0; hc < 4; hc++) {
            for (int idx = tid; idx < 32 * ED; idx += NTHREADS)
                sbuf[idx] = Ow[hc * 32 * ED + idx];   // [hh*64 + e]
            __syncthreads();
            #pragma unroll 4
            for (int hh = 0; hh < 32; hh++) {
                float w0 = sbuf[hh * 64 + lane];
                float w1 = sbuf[hh * 64 + 32 + lane];
                #pragma unroll
                for (int i = 0; i < 8; i++) {
                    int n = w + 16 * i;
                    if (n < NNEI) {
                        float ov = sq[n * HD + hc * 32 + hh];
                        accA[i] = fmaf(ov, w0, accA[i]);
                        accB[i] = fmaf(ov, w1, accB[i]);
                    }
                }
            }
            __syncthreads();
        }
        {
            float ob0 = out_b[l * ED + lane],      ob1 = out_b[l * ED + 32 + lane];
            float g0  = ln_g[l * ED + lane],       g1  = ln_g[l * ED + 32 + lane];
            float bb0 = ln_b[l * ED + lane],       bb1 = ln_b[l * ED + 32 + lane];
            #pragma unroll
            for (int i = 0; i < 8; i++) {
                int n = w + 16 * i;
                if (n < NNEI) {
                    float x0 = sx[n * ED + lane]      + accA[i] + ob0;
                    float x1 = sx[n * ED + 32 + lane] + accB[i] + ob1;
                    float mu = warp_sum(x0 + x1) * (1.0f / 64.0f);
                    float d0 = x0 - mu, d1 = x1 - mu;
                    float var = warp_sum(d0 * d0 + d1 * d1) * (1.0f / 64.0f);
                    float rs = rsqrtf(var + LN_EPS);
                    sx[n * ED + lane]      = d0 * rs * g0 + bb0;
                    sx[n * ED + 32 + lane] = d1 * rs * g1 + bb1;
                }
            }
        }
        __syncthreads();
    }

    // ---- write output ----
    float4* outp = (float4*)(out + (size_t)b * NNEI * ED);
    for (int i = tid; i < NNEI * ED / 4; i += NTHREADS) outp[i] = sx4[i];
}

extern "C" void kernel_launch(void* const* d_in, const int* in_sizes, int n_in,
                              void* d_out, int out_size) {
    const float* G     = (const float*)d_in[0];
    const int* mk      = (const int*)d_in[1];      // bool -> int32 per harness dtypes
    const float* r     = (const float*)d_in[2];
    const float* in_w  = (const float*)d_in[3];
    const float* in_b  = (const float*)d_in[4];
    const float* out_w = (const float*)d_in[5];
    const float* out_b = (const float*)d_in[6];
    const float* ln_g  = (const float*)d_in[7];
    const float* ln_b  = (const float*)d_in[8];
    float* out         = (float*)d_out;

    int B = in_sizes[0] / (NNEI * ED);

    cudaFuncSetAttribute(nwa_kernel, cudaFuncAttributeMaxDynamicSharedMemorySize,
                         SMEM_FLOATS * sizeof(float));
    nwa_kernel<<<B, NTHREADS, SMEM_FLOATS * sizeof(float)>>>(
        G, mk, r, in_w, in_b, out_w, out_b, ln_g, ln_b, out);
}

// round 3
// speedup vs baseline: 1.0017x; 1.0017x over previous
#include <cuda_runtime.h>
#include <math.h>

#define L_LAYERS 2
#define NNEI 120
#define ED 64
#define HD 128
#define FDIM 384          // 3*HD
#define NW 16
#define NTHREADS (NW * 32)
#define SCALING 0.08838834764831845f   // HD^-0.5
#define LN_EPS 1e-5f

// shared memory layout (in floats)
#define OFF_SX   0                         // 120*64   = 7680
#define OFF_SQ   7680                      // 120*128  = 15360 (q, later o)
#define OFF_SKT  23040                     // 128*120  = 15360 (k transposed)
#define OFF_SV   38400                     // 120*128  = 15360
#define OFF_BUF  53760                     // max(2048 weight chunk, 16*2*120 aw) = 3840
#define OFF_R    57600                     // 120*3 = 360
#define OFF_MASK 57960                     // 120
#define SMEM_FLOATS 58080                  // 232320 bytes <= 232448 limit

__device__ __forceinline__ float warp_sum(float v) {
    #pragma unroll
    for (int o = 16; o; o >>= 1) v += __shfl_xor_sync(0xffffffffu, v, o);
    return v;
}
__device__ __forceinline__ float warp_max(float v) {
    #pragma unroll
    for (int o = 16; o; o >>= 1) v = fmaxf(v, __shfl_xor_sync(0xffffffffu, v, o));
    return v;
}

// softmax + mask + angle weighting for one attention row; lane owns m=4*lane..+3
__device__ __forceinline__ void softmax_row(float4 a, int n, int lane, bool kvalid,
                                            const float* smask, const float* sr,
                                            float* awrow) {
    const float NEG = -1e30f;
    float lg[4] = {a.x, a.y, a.z, a.w};
    float mx = NEG;
    #pragma unroll
    for (int c = 0; c < 4; c++) {
        int m = 4 * lane + c;
        bool ok = kvalid && (smask[m & 127] > 0.5f);
        lg[c] = ok ? lg[c] : NEG;
        mx = fmaxf(mx, lg[c]);
    }
    mx = warp_max(mx);
    float ex[4]; float s = 0.f;
    #pragma unroll
    for (int c = 0; c < 4; c++) { ex[c] = __expf(lg[c] - mx); s += ex[c]; }
    s = warp_sum(s);
    float inv = 1.0f / s;
    float qm = smask[n];
    float rn0 = sr[n * 3 + 0], rn1 = sr[n * 3 + 1], rn2 = sr[n * 3 + 2];
    if (kvalid) {
        float pv[4];
        #pragma unroll
        for (int c = 0; c < 4; c++) {
            int m = 4 * lane + c;
            float ang = rn0 * sr[m * 3 + 0] + rn1 * sr[m * 3 + 1] + rn2 * sr[m * 3 + 2];
            pv[c] = ex[c] * inv * qm * ang;
        }
        ((float4*)awrow)[lane] = make_float4(pv[0], pv[1], pv[2], pv[3]);
    }
}

__global__ __launch_bounds__(NTHREADS, 1)
void nwa_kernel(const float* __restrict__ G,
                const int* __restrict__ maskp,          // bool arrives as int32
                const float* __restrict__ rp,
                const float* __restrict__ in_w, const float* __restrict__ in_b,
                const float* __restrict__ out_w, const float* __restrict__ out_b,
                const float* __restrict__ ln_g, const float* __restrict__ ln_b,
                float* __restrict__ out)
{
    extern __shared__ float sm[];
    float* sx   = sm + OFF_SX;
    float* sq   = sm + OFF_SQ;
    float* skT  = sm + OFF_SKT;
    float* sv   = sm + OFF_SV;
    float* sbuf = sm + OFF_BUF;
    float* sr   = sm + OFF_R;
    float* smask = sm + OFF_MASK;
    float4* sx4 = (float4*)sx;

    const int b = blockIdx.x;
    const int tid = threadIdx.x;
    const int w = tid >> 5;
    const int lane = tid & 31;

    // ---- load per-batch inputs ----
    {
        const float4* Gx = (const float4*)(G + (size_t)b * NNEI * ED);
        for (int i = tid; i < NNEI * ED / 4; i += NTHREADS) sx4[i] = Gx[i];
        const float* rb = rp + (size_t)b * NNEI * 3;
        for (int i = tid; i < NNEI * 3; i += NTHREADS) sr[i] = rb[i];
        if (tid < NNEI) smask[tid] = maskp[(size_t)b * NNEI + tid] ? 1.0f : 0.0f;
    }
    __syncthreads();

    for (int l = 0; l < L_LAYERS; l++) {
        // ================= Phase A: qkv = x @ in_w + in_b =================
        const float* Wl = in_w + (size_t)l * ED * FDIM;
        for (int fc = 0; fc < FDIM / 32; fc++) {
            for (int idx = tid; idx < ED * 32; idx += NTHREADS) {
                int e = idx >> 5, j = idx & 31;
                sbuf[idx] = Wl[e * FDIM + fc * 32 + j];
            }
            __syncthreads();
            float acc[8];
            #pragma unroll
            for (int i = 0; i < 8; i++) acc[i] = 0.f;
            #pragma unroll
            for (int et = 0; et < 8; et++) {
                float wr[8];
                #pragma unroll
                for (int k2 = 0; k2 < 8; k2++) wr[k2] = sbuf[(et * 8 + k2) * 32 + lane];
                #pragma unroll
                for (int i = 0; i < 8; i++) {
                    int n = w + 16 * i;
                    if (n < NNEI) {
                        float4 x0 = sx4[n * 16 + et * 2];
                        float4 x1 = sx4[n * 16 + et * 2 + 1];
                        acc[i] = fmaf(wr[0], x0.x, acc[i]);
                        acc[i] = fmaf(wr[1], x0.y, acc[i]);
                        acc[i] = fmaf(wr[2], x0.z, acc[i]);
                        acc[i] = fmaf(wr[3], x0.w, acc[i]);
                        acc[i] = fmaf(wr[4], x1.x, acc[i]);
                        acc[i] = fmaf(wr[5], x1.y, acc[i]);
                        acc[i] = fmaf(wr[6], x1.z, acc[i]);
                        acc[i] = fmaf(wr[7], x1.w, acc[i]);
                    }
                }
            }
            int f = fc * 32 + lane;
            float bv = in_b[l * FDIM + f];
            #pragma unroll
            for (int i = 0; i < 8; i++) {
                int n = w + 16 * i;
                if (n < NNEI) {
                    float v = acc[i] + bv;
                    if (f < HD)            sq[n * HD + f] = v;
                    else if (f < 2 * HD)   skT[(f - HD) * NNEI + n] = v;
                    else                   sv[n * HD + (f - 2 * HD)] = v;
                }
            }
            __syncthreads();
        }

        // ================= Phase B: l2norm rows of q, k, v =================
        for (int task = w; task < 3 * NNEI; task += NW) {
            int type = task / NNEI;   // 0=q, 1=k, 2=v
            int n = task % NNEI;
            if (type != 1) {
                float* base = (type == 0 ? sq : sv) + n * HD;
                float4 vv = ((float4*)base)[lane];
                float s = vv.x * vv.x + vv.y * vv.y + vv.z * vv.z + vv.w * vv.w;
                s = warp_sum(s);
                float sc = 1.0f / fmaxf(sqrtf(s), 1e-12f);
                if (type == 0) sc *= SCALING;
                vv.x *= sc; vv.y *= sc; vv.z *= sc; vv.w *= sc;
                ((float4*)base)[lane] = vv;
            } else {
                float v0 = skT[(lane +  0) * NNEI + n];
                float v1 = skT[(lane + 32) * NNEI + n];
                float v2 = skT[(lane + 64) * NNEI + n];
                float v3 = skT[(lane + 96) * NNEI + n];
                float s = v0 * v0 + v1 * v1 + v2 * v2 + v3 * v3;
                s = warp_sum(s);
                float sc = 1.0f / fmaxf(sqrtf(s), 1e-12f);
                skT[(lane +  0) * NNEI + n] = v0 * sc;
                skT[(lane + 32) * NNEI + n] = v1 * sc;
                skT[(lane + 64) * NNEI + n] = v2 * sc;
                skT[(lane + 96) * NNEI + n] = v3 * sc;
            }
        }
        __syncthreads();

        // ========= Phase C+E: attention (2 query rows per warp per group) =========
        const bool kvalid = (lane < 30);   // lane owns m = 4*lane..4*lane+3 (<120)
        for (int g = 0; g < 4; g++) {
            int base = g * 32 + w * 2;
            if (base < NNEI) {
                float4 a0 = make_float4(0, 0, 0, 0), a1 = make_float4(0, 0, 0, 0);
                for (int h = 0; h < HD; h++) {
                    float4 k4 = kvalid ? ((const float4*)(skT + h * NNEI))[lane]
                                       : make_float4(0, 0, 0, 0);
                    float q0 = sq[base * HD + h];
                    float q1 = sq[(base + 1) * HD + h];
                    a0.x = fmaf(q0, k4.x, a0.x); a0.y = fmaf(q0, k4.y, a0.y);
                    a0.z = fmaf(q0, k4.z, a0.z); a0.w = fmaf(q0, k4.w, a0.w);
                    a1.x = fmaf(q1, k4.x, a1.x); a1.y = fmaf(q1, k4.y, a1.y);
                    a1.z = fmaf(q1, k4.z, a1.z); a1.w = fmaf(q1, k4.w, a1.w);
                }
                float* aw0 = sbuf + w * 240;
                float* aw1 = aw0 + NNEI;
                softmax_row(a0, base,     lane, kvalid, smask, sr, aw0);
                softmax_row(a1, base + 1, lane, kvalid, smask, sr, aw1);
                __syncwarp();
                // o = aw @ v ; lane owns h = 4*lane..+3
                float4 o0 = make_float4(0, 0, 0, 0), o1 = make_float4(0, 0, 0, 0);
                for (int m = 0; m < NNEI; m++) {
                    float4 v4 = ((const float4*)(sv + m * HD))[lane];
                    float p0 = aw0[m], p1 = aw1[m];
                    o0.x = fmaf(p0, v4.x, o0.x); o0.y = fmaf(p0, v4.y, o0.y);
                    o0.z = fmaf(p0, v4.z, o0.z); o0.w = fmaf(p0, v4.w, o0.w);
                    o1.x = fmaf(p1, v4.x, o1.x); o1.y = fmaf(p1, v4.y, o1.y);
                    o1.z = fmaf(p1, v4.z, o1.z); o1.w = fmaf(p1, v4.w, o1.w);
                }
                ((float4*)(sq + base * HD))[lane] = o0;          // overwrite q with o
                ((float4*)(sq + (base + 1) * HD))[lane] = o1;
            }
            __syncwarp();
        }
        __syncthreads();

        // ====== Phase F: x = LN(residual + o @ out_w + out_b) ======
        float accA[8], accB[8];
        #pragma unroll
        for (int i = 0; i < 8; i++) { accA[i] = 0.f; accB[i] = 0.f; }
        const float* Ow = out_w + (size_t)l * HD * ED;
        for (int hc = 0; hc < 4; hc++) {
            for (int idx = tid; idx < 32 * ED; idx += NTHREADS)
                sbuf[idx] = Ow[hc * 32 * ED + idx];   // [hh*64 + e]
            __syncthreads();
            #pragma unroll 4
            for (int hh = 0; hh < 32; hh++) {
                float w0 = sbuf[hh * 64 + lane];
                float w1 = sbuf[hh * 64 + 32 + lane];
                #pragma unroll
                for (int i = 0; i < 8; i++) {
                    int n = w + 16 * i;
                    if (n < NNEI) {
                        float ov = sq[n * HD + hc * 32 + hh];
                        accA[i] = fmaf(ov, w0, accA[i]);
                        accB[i] = fmaf(ov, w1, accB[i]);
                    }
                }
            }
            __syncthreads();
        }
        {
            float ob0 = out_b[l * ED + lane],      ob1 = out_b[l * ED + 32 + lane];
            float g0  = ln_g[l * ED + lane],       g1  = ln_g[l * ED + 32 + lane];
            float bb0 = ln_b[l * ED + lane],       bb1 = ln_b[l * ED + 32 + lane];
            #pragma unroll
            for (int i = 0; i < 8; i++) {
                int n = w + 16 * i;
                if (n < NNEI) {
                    float x0 = sx[n * ED + lane]      + accA[i] + ob0;
                    float x1 = sx[n * ED + 32 + lane] + accB[i] + ob1;
                    float mu = warp_sum(x0 + x1) * (1.0f / 64.0f);
                    float d0 = x0 - mu, d1 = x1 - mu;
                    float var = warp_sum(d0 * d0 + d1 * d1) * (1.0f / 64.0f);
                    float rs = rsqrtf(var + LN_EPS);
                    sx[n * ED + lane]      = d0 * rs * g0 + bb0;
                    sx[n * ED + 32 + lane] = d1 * rs * g1 + bb1;
                }
            }
        }
        __syncthreads();
    }

    // ---- write output ----
    float4* outp = (float4*)(out + (size_t)b * NNEI * ED);
    for (int i = tid; i < NNEI * ED / 4; i += NTHREADS) outp[i] = sx4[i];
}

extern "C" void kernel_launch(void* const* d_in, const int* in_sizes, int n_in,
                              void* d_out, int out_size) {
    const float* G     = (const float*)d_in[0];
    const int* mk      = (const int*)d_in[1];      // bool -> int32 per harness dtypes
    const float* r     = (const float*)d_in[2];
    const float* in_w  = (const float*)d_in[3];
    const float* in_b  = (const float*)d_in[4];
    const float* out_w = (const float*)d_in[5];
    const float* out_b = (const float*)d_in[6];
    const float* ln_g  = (const float*)d_in[7];
    const float* ln_b  = (const float*)d_in[8];
    float* out         = (float*)d_out;

    int B = in_sizes[0] / (NNEI * ED);

    cudaFuncSetAttribute(nwa_kernel, cudaFuncAttributeMaxDynamicSharedMemorySize,
                         SMEM_FLOATS * sizeof(float));
    nwa_kernel<<<B, NTHREADS, SMEM_FLOATS * sizeof(float)>>>(
        G, mk, r, in_w, in_b, out_w, out_b, ln_g, ln_b, out);
}